// round 9
// baseline (speedup 1.0000x reference)
#include <cuda_runtime.h>
#include <cuda_bf16.h>

// Problem constants
#define Bb   16
#define Nn   1024
#define DIN  128
#define Hh   4
#define Dd   32
#define HD   128   // H*D

// Scratch (device globals; no allocation allowed)
__device__ float        g_h[Bb * Nn * HD];         // 8 MB: h = x@W + b, [b][n][head][d]
__device__ float        g_eit[Bb * Hh * Nn];       // e_i * log2(e), [b][head][n]
__device__ float        g_ejt[Bb * Hh * Nn];       // e_j * log2(e), [b][head][n]
// Interleaved bit masks: for 128-entry group g, word 4g+k bit L = adj[128g+4L+k]>0
__device__ unsigned int g_adjm[Bb * Nn * Nn / 32]; // 2 MB

__device__ __forceinline__ float ex2f(float x) {
    float y;
    asm("ex2.approx.ftz.f32 %0, %1;" : "=f"(y) : "f"(x));
    return y;
}

// ---------------------------------------------------------------------------
// Kernel 1: h = x @ W + b     (16384 x 128) @ (128 x 128)
// Epilogue also computes e_i/e_j (pre-scaled by log2 e) via 8-lane segmented
// reduction: lane tx owns cols 4tx..4tx+3 -> head = tx>>3; the 8-lane group
// (tx&7) spans exactly one head's D=32, so shfl_xor offsets 4,2,1 reduce it.
// ---------------------------------------------------------------------------
__global__ __launch_bounds__(256) void gemm_h_kernel(
    const float* __restrict__ x, const float* __restrict__ W,
    const float* __restrict__ bias, const float* __restrict__ a)
{
    __shared__ float Ws[32][128];   // 16 KB
    __shared__ float xs[64][32];    //  8 KB

    const int r0 = blockIdx.x * 64;
    const int tid = threadIdx.x;
    const int tx = tid & 31;        // col group: cols tx*4 .. tx*4+3
    const int ty = tid >> 5;        // row group: rows ty, ty+8, ..., ty+56

    float acc[8][4];
#pragma unroll
    for (int r = 0; r < 8; r++)
#pragma unroll
        for (int c = 0; c < 4; c++) acc[r][c] = 0.0f;

    for (int kt = 0; kt < 4; kt++) {
        const int k0 = kt * 32;
        __syncthreads();
#pragma unroll
        for (int q = 0; q < 2; q++) {
            int f = tid * 2 + q;            // 0..511
            int row = f >> 3;
            int c4  = f & 7;
            *(float4*)&xs[row][c4 * 4] =
                *(const float4*)&x[(r0 + row) * DIN + k0 + c4 * 4];
        }
#pragma unroll
        for (int q = 0; q < 4; q++) {
            int f = tid * 4 + q;            // 0..1023
            int row = f >> 5;
            int c4  = f & 31;
            *(float4*)&Ws[row][c4 * 4] =
                *(const float4*)&W[(k0 + row) * HD + c4 * 4];
        }
        __syncthreads();

#pragma unroll
        for (int k = 0; k < 32; k++) {
            float4 w4 = *(float4*)&Ws[k][tx * 4];
#pragma unroll
            for (int r = 0; r < 8; r++) {
                float xv = xs[ty + r * 8][k];
                acc[r][0] += xv * w4.x;
                acc[r][1] += xv * w4.y;
                acc[r][2] += xv * w4.z;
                acc[r][3] += xv * w4.w;
            }
        }
    }

    // per-lane attention-vector slice: d0 = (tx&7)*4 within this lane's head
    const int d0 = (tx & 7) * 4;
    const float4 ai4 = *(const float4*)&a[d0];        // a_i slice
    const float4 aj4 = *(const float4*)&a[Dd + d0];   // a_j slice
    const int head = tx >> 3;
    const float LOG2E = 1.4426950408889634f;

    float4 b4 = *(const float4*)&bias[tx * 4];
#pragma unroll
    for (int r = 0; r < 8; r++) {
        int row = r0 + ty + r * 8;
        float4 o;
        o.x = acc[r][0] + b4.x;
        o.y = acc[r][1] + b4.y;
        o.z = acc[r][2] + b4.z;
        o.w = acc[r][3] + b4.w;
        *(float4*)&g_h[row * HD + tx * 4] = o;

        // e_i / e_j partials for this (row, head)
        float si = o.x * ai4.x + o.y * ai4.y + o.z * ai4.z + o.w * ai4.w;
        float sj = o.x * aj4.x + o.y * aj4.y + o.z * aj4.z + o.w * aj4.w;
#pragma unroll
        for (int off = 4; off > 0; off >>= 1) {
            si += __shfl_xor_sync(0xffffffffu, si, off);
            sj += __shfl_xor_sync(0xffffffffu, sj, off);
        }
        if ((tx & 7) == 0) {
            int b  = row >> 10;
            int nn = row & 1023;
            int idx = (b * Hh + head) * Nn + nn;
            g_eit[idx] = si * LOG2E;
            g_ejt[idx] = sj * LOG2E;
        }
    }
}

// ---------------------------------------------------------------------------
// Kernel 2: adjacency -> interleaved bit masks.
// Thread loads int4 (coalesced); 4 ballots/warp cover 128 adj entries.
// Word 4g+k, bit L  <->  adj[128g + 4L + k] > 0.
// ---------------------------------------------------------------------------
__global__ __launch_bounds__(256) void adj_mask_kernel(const int* __restrict__ adj)
{
    const unsigned t4 = blockIdx.x * 256u + threadIdx.x;   // int4 index, 0..4M-1
    const int4 v = ((const int4*)adj)[t4];
    unsigned b0 = __ballot_sync(0xffffffffu, v.x > 0);
    unsigned b1 = __ballot_sync(0xffffffffu, v.y > 0);
    unsigned b2 = __ballot_sync(0xffffffffu, v.z > 0);
    unsigned b3 = __ballot_sync(0xffffffffu, v.w > 0);
    const unsigned lane = threadIdx.x & 31u;
    const unsigned g = t4 >> 5;                            // 128-entry group id
    if (lane < 4u) {
        unsigned w = (lane == 0u) ? b0 : (lane == 1u) ? b1 : (lane == 2u) ? b2 : b3;
        g_adjm[g * 4u + lane] = w;
    }
}

// ---------------------------------------------------------------------------
// Kernel 3: masked-softmax attention + aggregation.
// Block = (b, head, 128 i-rows). 256 threads = 8 warps.
// Thread owns one i-row; D=32 accumulator held as 16 packed f32x2 (b64) regs,
// updated with Blackwell fma.rn.f32x2 (2 MACs / instr).
// Warp halves split each 128-j tile: half0 -> jj [0,64), half1 -> jj [64,128),
// consumed in interleaved order jj = jb + 4t + k (sum is commutative).
// Epilogue merges halves through smem.
// ---------------------------------------------------------------------------
#define JT 128
__global__ __launch_bounds__(256, 4) void attn_kernel(float* __restrict__ out)
{
    __shared__ float Hs[JT][36];          // 18 KB padded (+4); 144B row stride (16B aligned)
    __shared__ float ejs[JT];             // 0.5 KB

    const int bid   = blockIdx.x;              // 0..511
    const int itile = bid & 7;
    const int head  = (bid >> 3) & 3;
    const int b     = bid >> 5;
    const int i0    = itile * 128;

    const int tid  = threadIdx.x;
    const int half = tid >> 7;                 // 0 or 1
    const int il   = tid & 127;                // i local
    const int i    = i0 + il;

    const float ei = g_eit[(b * Hh + head) * Nn + i];
    const float* __restrict__ ejp = &g_ejt[(b * Hh + head) * Nn];
    const float* __restrict__ hbp = &g_h[b * Nn * HD + head * Dd];
    const unsigned* __restrict__ mp = &g_adjm[(b * Nn + i) * 32];   // 32 words/row

    unsigned long long acc[16];                // 16 x f32x2 = 32 float accumulators
#pragma unroll
    for (int q = 0; q < 16; q++) acc[q] = 0ULL;
    float l = 0.f;

    const int jb = half * 64;                  // this half's jj base within tile
    const int hshift = half * 16;              // bit range within each word

    for (int jt = 0; jt < Nn; jt += JT) {
        __syncthreads();
        // stage h tile: 128 rows x 32 floats = 1024 float4; 4 per thread
#pragma unroll
        for (int q = 0; q < 4; q++) {
            int f   = tid * 4 + q;            // 0..1023
            int row = f >> 3;
            int c4  = (f & 7) * 4;
            *(float4*)&Hs[row][c4] =
                *(const float4*)&hbp[(jt + row) * HD + c4];
        }
        if (tid < JT) ejs[tid] = ejp[jt + tid];
        __syncthreads();

        // 4 interleaved mask words for this 128-j group
        const uint4 mw = *(const uint4*)&mp[(jt >> 7) * 4];

#pragma unroll
        for (int k = 0; k < 4; k++) {
            unsigned m = ((k == 0) ? mw.x : (k == 1) ? mw.y : (k == 2) ? mw.z : mw.w)
                         >> hshift;
#pragma unroll
            for (int t = 0; t < 16; t++) {
                const int jj = jb + t * 4 + k;
                float e = ei + ejs[jj];
                e = fmaxf(e, 0.2f * e);                 // leaky relu (log2 domain: scale>0 ok)
                float p = ex2f(e);
                p = __int_as_float(__float_as_int(p) & (-(int)(m & 1u)));
                m >>= 1;
                l += p;
                unsigned long long pp;
                asm("mov.b64 %0, {%1, %1};" : "=l"(pp) : "r"(__float_as_uint(p)));
                const ulonglong2* __restrict__ hrow = (const ulonglong2*)&Hs[jj][0];
#pragma unroll
                for (int q = 0; q < 8; q++) {
                    ulonglong2 h2 = hrow[q];            // one LDS.128 = 4 floats
                    asm("fma.rn.f32x2 %0, %1, %2, %0;"
                        : "+l"(acc[2 * q])     : "l"(h2.x), "l"(pp));
                    asm("fma.rn.f32x2 %0, %1, %2, %0;"
                        : "+l"(acc[2 * q + 1]) : "l"(h2.y), "l"(pp));
                }
            }
        }
    }

    // merge the two j-halves through smem
    __syncthreads();
    if (half == 1) {
#pragma unroll
        for (int q = 0; q < 8; q++) {
            ulonglong2 v;
            v.x = acc[2 * q];
            v.y = acc[2 * q + 1];
            *(ulonglong2*)&Hs[il][q * 4] = v;
        }
        ejs[il] = l;
    }
    __syncthreads();
    if (half == 0) {
        l += ejs[il];
        const float inv = 1.0f / l;
        float* op = out + ((size_t)(b * Nn + i) * HD) + head * Dd;
#pragma unroll
        for (int q = 0; q < 8; q++) {
            union { unsigned long long u; float2 f; } c0, c1;
            c0.u = acc[2 * q];
            c1.u = acc[2 * q + 1];
            float4 h4 = *(const float4*)&Hs[il][q * 4];   // other half's partial
            float4 o;
            o.x = (c0.f.x + h4.x) * inv;
            o.y = (c0.f.y + h4.y) * inv;
            o.z = (c1.f.x + h4.z) * inv;
            o.w = (c1.f.y + h4.w) * inv;
            *(float4*)&op[q * 4] = o;
        }
    }
}

// ---------------------------------------------------------------------------
extern "C" void kernel_launch(void* const* d_in, const int* in_sizes, int n_in,
                              void* d_out, int out_size)
{
    const float* x    = (const float*)d_in[0];
    const int*   adj  = (const int*)d_in[1];
    const float* W    = (const float*)d_in[2];
    const float* bias = (const float*)d_in[3];
    const float* a    = (const float*)d_in[4];
    float* out = (float*)d_out;

    adj_mask_kernel<<<(Bb * Nn * Nn) / (256 * 4), 256>>>(adj);
    gemm_h_kernel<<<(Bb * Nn) / 64, 256>>>(x, W, bias, a);
    attn_kernel<<<Bb * Hh * (Nn / 128), 256>>>(out);
}

// round 17
// speedup vs baseline: 1.7278x; 1.7278x over previous
#include <cuda_runtime.h>
#include <cuda_bf16.h>

// Problem constants
#define Bb   16
#define Nn   1024
#define DIN  128
#define Hh   4
#define Dd   32
#define HD   128   // H*D

// Scratch (device globals; no allocation allowed)
__device__ float        g_h[Bb * Nn * HD];         // 8 MB: h = x@W + b, [b][n][head][d]
__device__ float        g_eit[Bb * Hh * Nn];       // e_i * log2(e), [b][head][n]
__device__ float        g_ejt[Bb * Hh * Nn];       // e_j * log2(e), [b][head][n]
// Interleaved bit masks: for 128-entry group g, word 4g+k bit L = adj[128g+4L+k]>0
__device__ unsigned int g_adjm[Bb * Nn * Nn / 32]; // 2 MB

__device__ __forceinline__ float ex2f(float x) {
    float y;
    asm("ex2.approx.ftz.f32 %0, %1;" : "=f"(y) : "f"(x));
    return y;
}

// ---------------------------------------------------------------------------
// Kernel 1: h = x @ W + b     (16384 x 128) @ (128 x 128)
// Epilogue also computes e_i/e_j (pre-scaled by log2 e) via 8-lane segmented
// reduction: lane tx owns cols 4tx..4tx+3 -> head = tx>>3; the 8-lane group
// (tx&7) spans exactly one head's D=32, so shfl_xor offsets 4,2,1 reduce it.
// ---------------------------------------------------------------------------
__global__ __launch_bounds__(256) void gemm_h_kernel(
    const float* __restrict__ x, const float* __restrict__ W,
    const float* __restrict__ bias, const float* __restrict__ a)
{
    __shared__ float Ws[32][128];   // 16 KB
    __shared__ float xs[64][32];    //  8 KB

    const int r0 = blockIdx.x * 64;
    const int tid = threadIdx.x;
    const int tx = tid & 31;        // col group: cols tx*4 .. tx*4+3
    const int ty = tid >> 5;        // row group: rows ty, ty+8, ..., ty+56

    float acc[8][4];
#pragma unroll
    for (int r = 0; r < 8; r++)
#pragma unroll
        for (int c = 0; c < 4; c++) acc[r][c] = 0.0f;

    for (int kt = 0; kt < 4; kt++) {
        const int k0 = kt * 32;
        __syncthreads();
#pragma unroll
        for (int q = 0; q < 2; q++) {
            int f = tid * 2 + q;            // 0..511
            int row = f >> 3;
            int c4  = f & 7;
            *(float4*)&xs[row][c4 * 4] =
                *(const float4*)&x[(r0 + row) * DIN + k0 + c4 * 4];
        }
#pragma unroll
        for (int q = 0; q < 4; q++) {
            int f = tid * 4 + q;            // 0..1023
            int row = f >> 5;
            int c4  = f & 31;
            *(float4*)&Ws[row][c4 * 4] =
                *(const float4*)&W[(k0 + row) * HD + c4 * 4];
        }
        __syncthreads();

#pragma unroll
        for (int k = 0; k < 32; k++) {
            float4 w4 = *(float4*)&Ws[k][tx * 4];
#pragma unroll
            for (int r = 0; r < 8; r++) {
                float xv = xs[ty + r * 8][k];
                acc[r][0] += xv * w4.x;
                acc[r][1] += xv * w4.y;
                acc[r][2] += xv * w4.z;
                acc[r][3] += xv * w4.w;
            }
        }
    }

    // per-lane attention-vector slice: d0 = (tx&7)*4 within this lane's head
    const int d0 = (tx & 7) * 4;
    const float4 ai4 = *(const float4*)&a[d0];        // a_i slice
    const float4 aj4 = *(const float4*)&a[Dd + d0];   // a_j slice
    const int head = tx >> 3;
    const float LOG2E = 1.4426950408889634f;

    float4 b4 = *(const float4*)&bias[tx * 4];
#pragma unroll
    for (int r = 0; r < 8; r++) {
        int row = r0 + ty + r * 8;
        float4 o;
        o.x = acc[r][0] + b4.x;
        o.y = acc[r][1] + b4.y;
        o.z = acc[r][2] + b4.z;
        o.w = acc[r][3] + b4.w;
        *(float4*)&g_h[row * HD + tx * 4] = o;

        // e_i / e_j partials for this (row, head)
        float si = o.x * ai4.x + o.y * ai4.y + o.z * ai4.z + o.w * ai4.w;
        float sj = o.x * aj4.x + o.y * aj4.y + o.z * aj4.z + o.w * aj4.w;
#pragma unroll
        for (int off = 4; off > 0; off >>= 1) {
            si += __shfl_xor_sync(0xffffffffu, si, off);
            sj += __shfl_xor_sync(0xffffffffu, sj, off);
        }
        if ((tx & 7) == 0) {
            int b  = row >> 10;
            int nn = row & 1023;
            int idx = (b * Hh + head) * Nn + nn;
            g_eit[idx] = si * LOG2E;
            g_ejt[idx] = sj * LOG2E;
        }
    }
}

// ---------------------------------------------------------------------------
// Kernel 2: adjacency -> interleaved bit masks (measured 19.0us).
// Thread loads int4 (coalesced); 4 ballots/warp cover 128 adj entries.
// Word 4g+k, bit L  <->  adj[128g + 4L + k] > 0.
// ---------------------------------------------------------------------------
__global__ __launch_bounds__(256) void adj_mask_kernel(const int* __restrict__ adj)
{
    const unsigned t4 = blockIdx.x * 256u + threadIdx.x;   // int4 index, 0..4M-1
    const int4 v = ((const int4*)adj)[t4];
    unsigned b0 = __ballot_sync(0xffffffffu, v.x > 0);
    unsigned b1 = __ballot_sync(0xffffffffu, v.y > 0);
    unsigned b2 = __ballot_sync(0xffffffffu, v.z > 0);
    unsigned b3 = __ballot_sync(0xffffffffu, v.w > 0);
    const unsigned lane = threadIdx.x & 31u;
    const unsigned g = t4 >> 5;                            // 128-entry group id
    if (lane < 4u) {
        unsigned w = (lane == 0u) ? b0 : (lane == 1u) ? b1 : (lane == 2u) ? b2 : b3;
        g_adjm[g * 4u + lane] = w;
    }
}

// ---------------------------------------------------------------------------
// Kernel 3: masked-softmax attention + aggregation.  SPLIT-D layout.
// Block = (b, head, 128 i-rows). 256 threads: 2 threads per i-row,
// each owns HALF the head dim (D=16 -> acc = 8 x f32x2 = 16 regs).
// Each thread walks ALL 1024 j; both row-threads compute identical l,
// so there is no merge epilogue. ~50 regs total: no spill at occ 4.
// Mask consumption: jj = 4t + k matches interleaved producer layout.
// ---------------------------------------------------------------------------
#define JT 128
__global__ __launch_bounds__(256, 4) void attn_kernel(float* __restrict__ out)
{
    __shared__ float Hs[JT][36];          // 18 KB padded; 144B row stride (16B aligned)
    __shared__ float ejs[JT];             // 0.5 KB

    const int bid   = blockIdx.x;              // 0..511
    const int itile = bid & 7;
    const int head  = (bid >> 3) & 3;
    const int b     = bid >> 5;
    const int i0    = itile * 128;

    const int tid = threadIdx.x;
    const int il  = tid >> 1;                  // i local 0..127
    const int dh  = tid & 1;                   // d-half: 0 -> d[0,16), 1 -> d[16,32)
    const int i   = i0 + il;

    const float ei = g_eit[(b * Hh + head) * Nn + i];
    const float* __restrict__ ejp = &g_ejt[(b * Hh + head) * Nn];
    const float* __restrict__ hbp = &g_h[b * Nn * HD + head * Dd];
    const unsigned* __restrict__ mp = &g_adjm[(b * Nn + i) * 32];   // 32 words/row

    unsigned long long acc[8];                 // 8 x f32x2 = 16 float accumulators
#pragma unroll
    for (int q = 0; q < 8; q++) acc[q] = 0ULL;
    float l = 0.f;

    const int dbyte = dh * 64;                 // byte offset of this thread's d-half

    for (int jt = 0; jt < Nn; jt += JT) {
        __syncthreads();
        // stage h tile: 128 rows x 32 floats = 1024 float4; 4 per thread
#pragma unroll
        for (int q = 0; q < 4; q++) {
            int f   = tid * 4 + q;            // 0..1023
            int row = f >> 3;
            int c4  = (f & 7) * 4;
            *(float4*)&Hs[row][c4] =
                *(const float4*)&hbp[(jt + row) * HD + c4];
        }
        if (tid < JT) ejs[tid] = ejp[jt + tid];
        __syncthreads();

        const unsigned* __restrict__ mw = &mp[(jt >> 7) * 4];

#pragma unroll
        for (int k = 0; k < 4; k++) {
            unsigned m = mw[k];
            // row jj = 4t + k; byte addr of this thread's d-half in that row
            const char* hrow = (const char*)&Hs[0][0] + (unsigned)k * 144u + dbyte;
            const float* ejq = &ejs[k];
#pragma unroll 8
            for (int t = 0; t < 32; t++) {
                float e = ei + ejq[t * 4];              // ejs[4t+k], broadcast LDS
                e = fmaxf(e, 0.2f * e);                 // leaky relu (log2 domain ok)
                float p = ex2f(e);
                p = __int_as_float(__float_as_int(p) & (-(int)(m & 1u)));
                m >>= 1;
                l += p;
                unsigned long long pp;
                asm("mov.b64 %0, {%1, %1};" : "=l"(pp) : "r"(__float_as_uint(p)));
                const ulonglong2* __restrict__ hr =
                    (const ulonglong2*)(hrow + (unsigned)t * 576u);
#pragma unroll
                for (int q = 0; q < 4; q++) {
                    ulonglong2 h2 = hr[q];              // one LDS.128 = 4 floats
                    asm("fma.rn.f32x2 %0, %1, %2, %0;"
                        : "+l"(acc[2 * q])     : "l"(h2.x), "l"(pp));
                    asm("fma.rn.f32x2 %0, %1, %2, %0;"
                        : "+l"(acc[2 * q + 1]) : "l"(h2.y), "l"(pp));
                }
            }
        }
    }

    // no merge needed: both threads of a row computed the same l
    const float inv = 1.0f / l;
    float* op = out + ((size_t)(b * Nn + i) * HD) + head * Dd + dh * 16;
#pragma unroll
    for (int q = 0; q < 4; q++) {
        union { unsigned long long u; float2 f; } c0, c1;
        c0.u = acc[2 * q];
        c1.u = acc[2 * q + 1];
        float4 o;
        o.x = c0.f.x * inv;
        o.y = c0.f.y * inv;
        o.z = c1.f.x * inv;
        o.w = c1.f.y * inv;
        *(float4*)&op[q * 4] = o;
    }
}

// ---------------------------------------------------------------------------
extern "C" void kernel_launch(void* const* d_in, const int* in_sizes, int n_in,
                              void* d_out, int out_size)
{
    const float* x    = (const float*)d_in[0];
    const int*   adj  = (const int*)d_in[1];
    const float* W    = (const float*)d_in[2];
    const float* bias = (const float*)d_in[3];
    const float* a    = (const float*)d_in[4];
    float* out = (float*)d_out;

    adj_mask_kernel<<<(Bb * Nn * Nn) / (256 * 4), 256>>>(adj);
    gemm_h_kernel<<<(Bb * Nn) / 64, 256>>>(x, W, bias, a);
    attn_kernel<<<Bb * Hh * (Nn / 128), 256>>>(out);
}